// round 15
// baseline (speedup 1.0000x reference)
#include <cuda_runtime.h>
#include <cuda_bf16.h>
#include <float.h>
#include <stdint.h>

#define HH 4
#define BB 1024
#define DQv 512
#define DFv 128
#define DD1 128
#define DD2 64

__device__ float g_Wq[HH * DQv * DD2];
__device__ float g_bq[HH * DD2];
__device__ float g_bc[HH * 128];
__device__ float g_fq[BB * HH * DD2];
__device__ __nv_bfloat16 g_B0[HH * 128 * 128];   // [h][c][k]
__device__ __nv_bfloat16 g_B1[HH * 128 * 128];
__device__ __nv_bfloat16 g_A0[(long)BB * 200 * 128];  // [b][l][k]
__device__ __nv_bfloat16 g_A1[(long)BB * 200 * 128];

__device__ __forceinline__ float silu_f(float x) { return __fdividef(x, 1.f + __expf(-x)); }
__device__ __forceinline__ uint32_t smem_u32(const void* p) {
    uint32_t a;
    asm("{ .reg .u64 t; cvta.to.shared.u64 t, %1; cvt.u32.u64 %0, t; }" : "=r"(a) : "l"(p));
    return a;
}
__device__ __forceinline__ uint32_t bf2pack(float lo, float hi) {
    uint32_t r;
    asm("cvt.rn.bf16x2.f32 %0, %1, %2;" : "=r"(r) : "f"(hi), "f"(lo));
    return r;
}
__device__ __forceinline__ float bflo(uint32_t q) { return __uint_as_float(q << 16); }
__device__ __forceinline__ float bfhi(uint32_t q) { return __uint_as_float(q & 0xffff0000u); }

__device__ __forceinline__ void ldm_x4(uint32_t a[4], uint32_t addr) {
    asm volatile("ldmatrix.sync.aligned.m8n8.x4.shared.b16 {%0,%1,%2,%3}, [%4];"
        : "=r"(a[0]), "=r"(a[1]), "=r"(a[2]), "=r"(a[3]) : "r"(addr));
}
__device__ __forceinline__ void mma16816(float d[4], const uint32_t a[4], const uint32_t b[2]) {
    asm volatile(
        "mma.sync.aligned.m16n8k16.row.col.f32.bf16.bf16.f32 "
        "{%0,%1,%2,%3}, {%4,%5,%6,%7}, {%8,%9}, {%0,%1,%2,%3};"
        : "+f"(d[0]), "+f"(d[1]), "+f"(d[2]), "+f"(d[3])
        : "r"(a[0]), "r"(a[1]), "r"(a[2]), "r"(a[3]), "r"(b[0]), "r"(b[1]));
}
__device__ __forceinline__ void cp16(uint32_t dst, const void* src) {
    asm volatile("cp.async.cg.shared.global [%0], [%1], 16;" :: "r"(dst), "l"(src));
}
#define CP_COMMIT()      asm volatile("cp.async.commit_group;" ::: "memory")
#define CP_WAIT0()       asm volatile("cp.async.wait_group 0;" ::: "memory")

// ---------------- prekernels ----------------
__global__ void collapse_q_kernel(const float* __restrict__ Wq1, const float* __restrict__ bq1,
                                  const float* __restrict__ Wq2, const float* __restrict__ bq2) {
    int idx = blockIdx.x * 256 + threadIdx.x;
    int c = idx & 63, k = (idx >> 6) & 511, h = idx >> 15;
    const float* a  = Wq1 + (h * DQv + k) * DD1;
    const float* w2 = Wq2 + h * DD1 * DD2 + c;
    float acc = 0.f;
#pragma unroll 8
    for (int j = 0; j < DD1; ++j) acc += a[j] * w2[j * DD2];
    g_Wq[idx] = acc;
    if (k == 0) {
        float bb = bq2[h * DD2 + c];
        const float* b1p = bq1 + h * DD1;
#pragma unroll 8
        for (int j = 0; j < DD1; ++j) bb += b1p[j] * w2[j * DD2];
        g_bq[h * DD2 + c] = bb;
    }
}

__global__ void collapse_fvT_kernel(const float* __restrict__ Wf1, const float* __restrict__ bf1,
                                    const float* __restrict__ Wf2, const float* __restrict__ bf2,
                                    const float* __restrict__ Wv1, const float* __restrict__ bv1,
                                    const float* __restrict__ Wv2, const float* __restrict__ bv2) {
    int idx = blockIdx.x * 256 + threadIdx.x;
    int c = idx & 127, k = (idx >> 7) & 127, h = idx >> 14;
    const float *W1, *W2, *B1, *B2; int cc;
    if (c < 64) { W1 = Wf1; W2 = Wf2; B1 = bf1; B2 = bf2; cc = c; }
    else        { W1 = Wv1; W2 = Wv2; B1 = bv1; B2 = bv2; cc = c - 64; }
    const float* a  = W1 + (h * DFv + k) * DD1;
    const float* w2 = W2 + h * DD1 * DD2 + cc;
    float acc = 0.f;
#pragma unroll 8
    for (int j = 0; j < DD1; ++j) acc += a[j] * w2[j * DD2];
    int o = h * 16384 + c * 128 + k;
    __nv_bfloat16 q0 = __float2bfloat16(acc);
    float r1 = acc - __bfloat162float(q0);
    g_B0[o] = q0; g_B1[o] = __float2bfloat16(r1);
    if (k == 0) {
        float bb = B2[h * DD2 + cc];
        const float* b1p = B1 + h * DD1;
#pragma unroll 8
        for (int j = 0; j < DD1; ++j) bb += b1p[j] * w2[j * DD2];
        g_bc[h * 128 + c] = bb;
    }
}

__global__ __launch_bounds__(256) void presplit_fact(const float* __restrict__ fact) {
    long idx = (long)blockIdx.x * 256 + threadIdx.x;
    long base = idx * 8;
    float xv[8];
    *reinterpret_cast<float4*>(xv)     = *reinterpret_cast<const float4*>(fact + base);
    *reinterpret_cast<float4*>(xv + 4) = *reinterpret_cast<const float4*>(fact + base + 4);
    uint32_t p0[4], p1[4];
#pragma unroll
    for (int i = 0; i < 4; ++i) {
        float lo = xv[2 * i], hi = xv[2 * i + 1];
        uint32_t q0 = bf2pack(lo, hi);
        float rlo = lo - bflo(q0), rhi = hi - bfhi(q0);
        p0[i] = q0; p1[i] = bf2pack(rlo, rhi);
    }
    *reinterpret_cast<uint4*>(reinterpret_cast<char*>(g_A0) + base * 2) = make_uint4(p0[0], p0[1], p0[2], p0[3]);
    *reinterpret_cast<uint4*>(reinterpret_cast<char*>(g_A1) + base * 2) = make_uint4(p1[0], p1[1], p1[2], p1[3]);
}

// fq: grid 128 (32 bg x 4 h), 512 threads, k-split 2.
// smem (dynamic): qs[2][32*66] | ws[2][4096] | part[2][2048]
#define FQ_QS   0
#define FQ_WS   (2 * 32 * 66)
#define FQ_PART (FQ_WS + 2 * 4096)
#define FQ_SMEM ((FQ_PART + 2 * 2048) * 4)

__global__ __launch_bounds__(512) void fq_kernel(const float* __restrict__ query) {
    extern __shared__ float fsm[];
    float* qs   = fsm + FQ_QS;
    float* ws   = fsm + FQ_WS;
    float* part = fsm + FQ_PART;

    const int tid = threadIdx.x;
    const int half = tid >> 8;
    const int ht = tid & 255;
    const int h  = blockIdx.x & 3;
    const int bg = blockIdx.x >> 2;
    const int bl = (ht >> 4) * 2;
    const int cq = (ht & 15) * 4;

    float acc[8];
#pragma unroll
    for (int i = 0; i < 8; ++i) acc[i] = 0.f;

    for (int kc4 = 0; kc4 < 4; ++kc4) {
        int kc = half * 4 + kc4;
        __syncthreads();
#pragma unroll
        for (int it = 0; it < 8; ++it) {
            int idx = ht + it * 256;          // < 2048
            int bb = idx >> 6, kk = idx & 63;
            qs[half * 2112 + bb * 66 + kk] = query[(long)(bg * 32 + bb) * DQv + kc * 64 + kk];
        }
#pragma unroll
        for (int it = 0; it < 16; ++it) {
            int idx = ht + it * 256;          // < 4096
            ws[half * 4096 + idx] = g_Wq[(h * DQv + kc * 64 + (idx >> 6)) * DD2 + (idx & 63)];
        }
        __syncthreads();
#pragma unroll 4
        for (int k = 0; k < 64; ++k) {
            float qv0 = qs[half * 2112 + bl * 66 + k];
            float qv1 = qs[half * 2112 + (bl + 1) * 66 + k];
            float4 w4 = *reinterpret_cast<const float4*>(ws + half * 4096 + k * 64 + cq);
            acc[0] += qv0 * w4.x; acc[1] += qv0 * w4.y;
            acc[2] += qv0 * w4.z; acc[3] += qv0 * w4.w;
            acc[4] += qv1 * w4.x; acc[5] += qv1 * w4.y;
            acc[6] += qv1 * w4.z; acc[7] += qv1 * w4.w;
        }
    }
    __syncthreads();
#pragma unroll
    for (int r = 0; r < 2; ++r)
#pragma unroll
        for (int j = 0; j < 4; ++j)
            part[half * 2048 + (bl + r) * 64 + cq + j] = acc[r * 4 + j];
    __syncthreads();
    if (half == 0) {
#pragma unroll
        for (int j = 0; j < 8; ++j) {
            int o = ht * 8 + j;
            int bb = o >> 6, cc = o & 63;
            float val = part[o] + part[2048 + o] + g_bq[h * DD2 + cc];
            g_fq[(long)(bg * 32 + bb) * 256 + h * 64 + cc] = silu_f(val);
        }
    }
}

// ---------------- HMMA main kernel: one CTA per (2 b, h), 2 CTAs/SM ----------------
// bf16x2 split, 3 passes (a0b0, a0b1, a1b0). B staged once, reused for both b.
// A tiled 80/80/40; online softmax in v-warps; 8 warps = 4 ng(n32) x 2 mg.
#define AS_SPL 20480
#define BS_OFF 40960
#define BS_SPL 32768
#define SCR_OFF 106496
#define SMEM_BYTES 108544

template<int MT>
__device__ __forceinline__ void gemm32(uint32_t sbase, int nb, int mbase, int lane, float d[][16]) {
#pragma unroll
    for (int mt = 0; mt < MT; ++mt)
#pragma unroll
        for (int i = 0; i < 16; ++i) d[mt][i] = 0.f;

    const uint32_t xr = (uint32_t)(lane & 7);
    const uint32_t arow = (uint32_t)(mbase + (lane & 15)) * 256;
    const uint32_t achk = (uint32_t)(lane >> 4);
    const uint32_t bj  = (uint32_t)(lane >> 4);
    const uint32_t bchk = (uint32_t)((lane >> 3) & 1);
    const uint32_t brow_base = (uint32_t)(nb + bj * 8 + (lane & 7)) * 256;

#pragma unroll 1
    for (int ks = 0; ks < 8; ++ks) {
        uint32_t bf[2][2][4];
        const uint32_t bx = (((uint32_t)(2 * ks) + bchk) ^ xr) * 16;
#pragma unroll
        for (int s = 0; s < 2; ++s)
#pragma unroll
            for (int jp = 0; jp < 2; ++jp)
                ldm_x4(bf[s][jp], sbase + BS_OFF + s * BS_SPL + brow_base + (uint32_t)(jp * 16) * 256 + bx);
        const uint32_t ax = (((uint32_t)(2 * ks) + achk) ^ xr) * 16;
#pragma unroll
        for (int mt = 0; mt < MT; ++mt) {
            const uint32_t aoff = arow + (uint32_t)(mt * 16) * 256 + ax;
            uint32_t a0[4], a1[4];
            ldm_x4(a0, sbase + aoff);
            ldm_x4(a1, sbase + AS_SPL + aoff);
#pragma unroll
            for (int jp = 0; jp < 2; ++jp)
#pragma unroll
                for (int jj = 0; jj < 2; ++jj) {
                    int j = jp * 2 + jj;
                    mma16816(d[mt] + 4 * j, a0, bf[0][jp] + 2 * jj);
                    mma16816(d[mt] + 4 * j, a0, bf[1][jp] + 2 * jj);
                    mma16816(d[mt] + 4 * j, a1, bf[0][jp] + 2 * jj);
                }
        }
    }
}

__global__ __launch_bounds__(256, 2) void mha_hmma_kernel(
    const int* __restrict__ mask, const float* __restrict__ mm,
    const float* __restrict__ tau1, const float* __restrict__ tau2,
    float* __restrict__ out)
{
    extern __shared__ char smem[];
    float* scr = reinterpret_cast<float*>(smem + SCR_OFF);
    float* pd0 = scr;          // [80]
    float* pd1 = scr + 80;     // [80]
    float* lg_s = scr + 160;   // [80]
    float* mo  = scr + 240;    // [2][64]
    float* mp  = scr + 368;    // [2][64]
    float* mS  = scr + 496;    // [4]

    const int tid  = threadIdx.x;
    const int w    = tid >> 5;
    const int lane = tid & 31;
    const int g    = lane >> 2;
    const int t4   = lane & 3;
    const int b2 = blockIdx.x >> 2;
    const int h = blockIdx.x & 3;
    const int ng = w & 3;
    const int mg = w >> 2;
    const int nb = ng * 32;
    const bool is_f = (ng < 2);
    const uint32_t sbase = smem_u32(smem);

    float bcv[8];
#pragma unroll
    for (int j = 0; j < 4; ++j) {
        int c = nb + j * 8 + t4 * 2;
        bcv[2 * j]     = g_bc[h * 128 + c];
        bcv[2 * j + 1] = g_bc[h * 128 + c + 1];
    }

    const float t1a = tau1[h], t1b = tau1[4 + h];
    const float cb1v = tau2[h], cb2v = tau2[4 + h], cb3v = tau2[8 + h];

    // ---- stage B (once, both splits) + A tile0 of b0 ----
    {
        const __nv_bfloat16* bsrc[2] = {g_B0 + h * 16384, g_B1 + h * 16384};
#pragma unroll
        for (int it = 0; it < 16; ++it) {
            int idx = tid + it * 256;          // < 4096
            int s = idx >> 11, r = idx & 2047;
            int crow = r >> 4, c = r & 15;
            uint32_t dst = sbase + BS_OFF + s * BS_SPL + crow * 256 + ((c ^ (crow & 7)) * 16);
            cp16(dst, bsrc[s] + crow * 128 + c * 8);
        }
        const __nv_bfloat16* a0p = g_A0 + (long)(b2 * 2) * 25600;
        const __nv_bfloat16* a1p = g_A1 + (long)(b2 * 2) * 25600;
#pragma unroll
        for (int it = 0; it < 10; ++it) {
            int idx = tid + it * 256;          // < 2560
            int s = idx / 1280;
            int r = idx - s * 1280;
            int l = r >> 4, c = r & 15;
            uint32_t dst = sbase + s * AS_SPL + l * 256 + ((c ^ (l & 7)) * 16);
            const __nv_bfloat16* src = (s == 0 ? a0p : a1p) + (long)l * 128 + c * 8;
            cp16(dst, src);
        }
        CP_COMMIT(); CP_WAIT0();
    }
    __syncthreads();

#pragma unroll 1
    for (int bb = 0; bb < 2; ++bb) {
        const int b = b2 * 2 + bb;
        const __nv_bfloat16* asrc0 = g_A0 + (long)b * 25600;
        const __nv_bfloat16* asrc1 = g_A1 + (long)b * 25600;

        float fqv[8];
#pragma unroll
        for (int j = 0; j < 4; ++j) {
            if (is_f) {
                int c = nb + j * 8 + t4 * 2;
                fqv[2 * j]     = g_fq[b * 256 + h * 64 + c];
                fqv[2 * j + 1] = g_fq[b * 256 + h * 64 + c + 1];
            } else { fqv[2 * j] = 0.f; fqv[2 * j + 1] = 0.f; }
        }

        float m_run = -FLT_MAX, S_run = 0.f;
        float ov[8], pv[8];
#pragma unroll
        for (int i = 0; i < 8; ++i) { ov[i] = 0.f; pv[i] = 0.f; }

#pragma unroll 1
        for (int t = 0; t < 3; ++t) {
            const int tbase = t * 80;
            const int rowbase = (t < 2) ? (mg ? 48 : 0) : (mg ? 32 : 0);
            const int MT = (t < 2) ? (mg ? 2 : 3) : (mg ? 1 : 2);
            const int rows_t = (t < 2) ? 80 : 40;

            float d[3][16];
            if (t < 2) { if (mg == 0) gemm32<3>(sbase, nb, rowbase, lane, d);
                         else         gemm32<2>(sbase, nb, rowbase, lane, d); }
            else       { if (mg == 0) gemm32<2>(sbase, nb, rowbase, lane, d);
                         else         gemm32<1>(sbase, nb, rowbase, lane, d); }

            if (is_f) {
#pragma unroll
                for (int mt = 0; mt < 3; ++mt) {
                    if (mt < MT) {
                        float s0 = 0.f, s1 = 0.f;
#pragma unroll
                        for (int j = 0; j < 4; ++j) {
                            s0 += silu_f(d[mt][4*j]   + bcv[2*j])   * fqv[2*j]
                                + silu_f(d[mt][4*j+1] + bcv[2*j+1]) * fqv[2*j+1];
                            s1 += silu_f(d[mt][4*j+2] + bcv[2*j])   * fqv[2*j]
                                + silu_f(d[mt][4*j+3] + bcv[2*j+1]) * fqv[2*j+1];
                        }
                        s0 += __shfl_xor_sync(0xffffffffu, s0, 1); s0 += __shfl_xor_sync(0xffffffffu, s0, 2);
                        s1 += __shfl_xor_sync(0xffffffffu, s1, 1); s1 += __shfl_xor_sync(0xffffffffu, s1, 2);
                        if (t4 == 0) {
                            float* pdp = (ng == 0) ? pd0 : pd1;
                            pdp[rowbase + mt * 16 + g]     = s0;
                            pdp[rowbase + mt * 16 + g + 8] = s1;
                        }
                    }
                }
            }
            __syncthreads();   // A(t) consumed; pd visible

            // prefetch: next tile of this b, or tile0 of b+1
            bool pref = (t < 2) || (bb == 0);
            if (pref) {
                int ntb; int R;
                const __nv_bfloat16 *p0, *p1;
                if (t < 2) { ntb = tbase + 80; R = (t == 0) ? 80 : 40; p0 = asrc0; p1 = asrc1; }
                else       { ntb = 0; R = 80; p0 = asrc0 + 25600; p1 = asrc1 + 25600; }
                const int chunks = R * 16;
                for (int idx = tid; idx < 2 * chunks; idx += 256) {
                    int s = idx / chunks;
                    int r = idx - s * chunks;
                    int l = r >> 4, c = r & 15;
                    uint32_t dst = sbase + s * AS_SPL + l * 256 + ((c ^ (l & 7)) * 16);
                    const __nv_bfloat16* src = (s == 0 ? p0 : p1) + (long)(ntb + l) * 128 + c * 8;
                    cp16(dst, src);
                }
                CP_COMMIT();
            }

            if (tid < rows_t) {
                int l = tbase + tid;
                float dd = pd0[tid] + pd1[tid];
                float mk = (float)mask[b * 200 + l];
                dd += (-1e9f) * (1.f - mk);
                float bias = mm[b * 200 + l] / t1a + mm[204800 + b * 200 + l] / t1b;
                lg_s[tid] = cb1v * dd + cb2v * bias + cb3v * dd * bias;
            }
            __syncthreads();

            if (!is_f) {
#pragma unroll
                for (int mt = 0; mt < 3; ++mt) {
                    if (mt < MT) {
                        int loc0 = rowbase + mt * 16 + g;
#pragma unroll
                        for (int half = 0; half < 2; ++half) {
                            int loc = loc0 + half * 8;
                            int l = tbase + loc;
                            if (l < 200) {
                                float lg = lg_s[loc];
                                float mn = fmaxf(m_run, lg);
                                float sc = __expf(m_run - mn);
                                float e  = __expf(lg - mn);
                                S_run = S_run * sc + e;
#pragma unroll
                                for (int j = 0; j < 4; ++j) {
                                    float v0 = silu_f(d[mt][4*j + 2*half]     + bcv[2*j]);
                                    float v1 = silu_f(d[mt][4*j + 2*half + 1] + bcv[2*j+1]);
                                    ov[2*j]   = ov[2*j]   * sc + e * v0;  pv[2*j]   += v0;
                                    ov[2*j+1] = ov[2*j+1] * sc + e * v1;  pv[2*j+1] += v1;
                                }
                                m_run = mn;
                            }
                        }
                    }
                }
            }
            if (pref) CP_WAIT0();
            __syncthreads();
        }

        // ---- merge + output for this b ----
        if (!is_f) {
#pragma unroll
            for (int off = 4; off <= 16; off <<= 1) {
                float m2 = __shfl_xor_sync(0xffffffffu, m_run, off);
                float S2 = __shfl_xor_sync(0xffffffffu, S_run, off);
                float M = fmaxf(m_run, m2);
                float sa = __expf(m_run - M), sb = __expf(m2 - M);
                S_run = S_run * sa + S2 * sb;
#pragma unroll
                for (int i = 0; i < 8; ++i) {
                    float o2 = __shfl_xor_sync(0xffffffffu, ov[i], off);
                    float p2 = __shfl_xor_sync(0xffffffffu, pv[i], off);
                    ov[i] = ov[i] * sa + o2 * sb;
                    pv[i] += p2;
                }
                m_run = M;
            }
            if (lane < 4) {
#pragma unroll
                for (int j = 0; j < 4; ++j) {
                    int c = (ng - 2) * 32 + j * 8 + t4 * 2;
                    mo[mg * 64 + c]     = ov[2*j];
                    mo[mg * 64 + c + 1] = ov[2*j+1];
                    mp[mg * 64 + c]     = pv[2*j];
                    mp[mg * 64 + c + 1] = pv[2*j+1];
                }
                if (ng == 2 && lane == 0) { mS[mg] = m_run; mS[2 + mg] = S_run; }
            }
        }
        __syncthreads();

        if (tid < 64) {
            float m0 = mS[0], m1 = mS[1];
            float M = fmaxf(m0, m1);
            float e0 = __expf(m0 - M), e1 = __expf(m1 - M);
            float S = mS[2] * e0 + mS[3] * e1;
            float o = mo[tid] * e0 + mo[64 + tid] * e1;
            float p = mp[tid] + mp[64 + tid];
            out[b * 256 + h * 64 + tid] = __fdividef(o, S) + 1e-7f * p;
        }
        __syncthreads();
    }
}

extern "C" void kernel_launch(void* const* d_in, const int* in_sizes, int n_in,
                              void* d_out, int out_size) {
    const float* query = (const float*)d_in[0];
    const float* fact  = (const float*)d_in[1];
    const int*   mask  = (const int*)  d_in[2];
    const float* mm    = (const float*)d_in[3];
    const float* Wq1   = (const float*)d_in[4];
    const float* bq1   = (const float*)d_in[5];
    const float* Wq2   = (const float*)d_in[6];
    const float* bq2   = (const float*)d_in[7];
    const float* Wf1   = (const float*)d_in[8];
    const float* bf1   = (const float*)d_in[9];
    const float* Wf2   = (const float*)d_in[10];
    const float* bf2   = (const float*)d_in[11];
    const float* Wv1   = (const float*)d_in[12];
    const float* bv1   = (const float*)d_in[13];
    const float* Wv2   = (const float*)d_in[14];
    const float* bv2   = (const float*)d_in[15];
    const float* tau1  = (const float*)d_in[16];
    const float* tau2  = (const float*)d_in[17];
    float* out = (float*)d_out;

    cudaFuncSetAttribute(mha_hmma_kernel, cudaFuncAttributeMaxDynamicSharedMemorySize, SMEM_BYTES);
    cudaFuncSetAttribute(fq_kernel, cudaFuncAttributeMaxDynamicSharedMemorySize, FQ_SMEM);

    collapse_q_kernel<<<512, 256>>>(Wq1, bq1, Wq2, bq2);
    collapse_fvT_kernel<<<256, 256>>>(Wf1, bf1, Wf2, bf2, Wv1, bv1, Wv2, bv2);
    presplit_fact<<<12800, 256>>>(fact);
    fq_kernel<<<128, 512, FQ_SMEM>>>(query);
    mha_hmma_kernel<<<BB * HH / 2, 256, SMEM_BYTES>>>(mask, mm, tau1, tau2, out);
}

// round 16
// speedup vs baseline: 1.0721x; 1.0721x over previous
#include <cuda_runtime.h>
#include <cuda_bf16.h>
#include <float.h>
#include <stdint.h>

#define HH 4
#define BB 1024
#define DQv 512
#define DFv 128
#define DD1 128
#define DD2 64

__device__ float g_Wq[HH * DQv * DD2];
__device__ float g_bq[HH * DD2];
__device__ float g_bc[HH * 128];
__device__ float g_fq[BB * HH * DD2];
__device__ __nv_bfloat16 g_B0[HH * 128 * 128];   // [h][c][k]
__device__ __nv_bfloat16 g_B1[HH * 128 * 128];
__device__ __nv_bfloat16 g_A0[(long)BB * 200 * 128];  // [b][l][k]
__device__ __nv_bfloat16 g_A1[(long)BB * 200 * 128];

__device__ __forceinline__ float silu_f(float x) { return __fdividef(x, 1.f + __expf(-x)); }
__device__ __forceinline__ uint32_t smem_u32(const void* p) {
    uint32_t a;
    asm("{ .reg .u64 t; cvta.to.shared.u64 t, %1; cvt.u32.u64 %0, t; }" : "=r"(a) : "l"(p));
    return a;
}
__device__ __forceinline__ uint32_t bf2pack(float lo, float hi) {
    uint32_t r;
    asm("cvt.rn.bf16x2.f32 %0, %1, %2;" : "=r"(r) : "f"(hi), "f"(lo));
    return r;
}
__device__ __forceinline__ float bflo(uint32_t q) { return __uint_as_float(q << 16); }
__device__ __forceinline__ float bfhi(uint32_t q) { return __uint_as_float(q & 0xffff0000u); }

__device__ __forceinline__ void ldm_x4(uint32_t a[4], uint32_t addr) {
    asm volatile("ldmatrix.sync.aligned.m8n8.x4.shared.b16 {%0,%1,%2,%3}, [%4];"
        : "=r"(a[0]), "=r"(a[1]), "=r"(a[2]), "=r"(a[3]) : "r"(addr));
}
__device__ __forceinline__ void mma16816(float d[4], const uint32_t a[4], const uint32_t b[2]) {
    asm volatile(
        "mma.sync.aligned.m16n8k16.row.col.f32.bf16.bf16.f32 "
        "{%0,%1,%2,%3}, {%4,%5,%6,%7}, {%8,%9}, {%0,%1,%2,%3};"
        : "+f"(d[0]), "+f"(d[1]), "+f"(d[2]), "+f"(d[3])
        : "r"(a[0]), "r"(a[1]), "r"(a[2]), "r"(a[3]), "r"(b[0]), "r"(b[1]));
}
__device__ __forceinline__ void cp16(uint32_t dst, const void* src) {
    asm volatile("cp.async.cg.shared.global [%0], [%1], 16;" :: "r"(dst), "l"(src));
}
#define CP_COMMIT()      asm volatile("cp.async.commit_group;" ::: "memory")
#define CP_WAIT0()       asm volatile("cp.async.wait_group 0;" ::: "memory")

// ---------------- prekernels ----------------
__global__ void collapse_q_kernel(const float* __restrict__ Wq1, const float* __restrict__ bq1,
                                  const float* __restrict__ Wq2, const float* __restrict__ bq2) {
    int idx = blockIdx.x * 256 + threadIdx.x;
    int c = idx & 63, k = (idx >> 6) & 511, h = idx >> 15;
    const float* a  = Wq1 + (h * DQv + k) * DD1;
    const float* w2 = Wq2 + h * DD1 * DD2 + c;
    float acc = 0.f;
#pragma unroll 8
    for (int j = 0; j < DD1; ++j) acc += a[j] * w2[j * DD2];
    g_Wq[idx] = acc;
    if (k == 0) {
        float bb = bq2[h * DD2 + c];
        const float* b1p = bq1 + h * DD1;
#pragma unroll 8
        for (int j = 0; j < DD1; ++j) bb += b1p[j] * w2[j * DD2];
        g_bq[h * DD2 + c] = bb;
    }
}

__global__ void collapse_fvT_kernel(const float* __restrict__ Wf1, const float* __restrict__ bf1,
                                    const float* __restrict__ Wf2, const float* __restrict__ bf2,
                                    const float* __restrict__ Wv1, const float* __restrict__ bv1,
                                    const float* __restrict__ Wv2, const float* __restrict__ bv2) {
    int idx = blockIdx.x * 256 + threadIdx.x;
    int c = idx & 127, k = (idx >> 7) & 127, h = idx >> 14;
    const float *W1, *W2, *B1, *B2; int cc;
    if (c < 64) { W1 = Wf1; W2 = Wf2; B1 = bf1; B2 = bf2; cc = c; }
    else        { W1 = Wv1; W2 = Wv2; B1 = bv1; B2 = bv2; cc = c - 64; }
    const float* a  = W1 + (h * DFv + k) * DD1;
    const float* w2 = W2 + h * DD1 * DD2 + cc;
    float acc = 0.f;
#pragma unroll 8
    for (int j = 0; j < DD1; ++j) acc += a[j] * w2[j * DD2];
    int o = h * 16384 + c * 128 + k;
    __nv_bfloat16 q0 = __float2bfloat16(acc);
    float r1 = acc - __bfloat162float(q0);
    g_B0[o] = q0; g_B1[o] = __float2bfloat16(r1);
    if (k == 0) {
        float bb = B2[h * DD2 + cc];
        const float* b1p = B1 + h * DD1;
#pragma unroll 8
        for (int j = 0; j < DD1; ++j) bb += b1p[j] * w2[j * DD2];
        g_bc[h * 128 + c] = bb;
    }
}

__global__ __launch_bounds__(256) void presplit_fact(const float* __restrict__ fact) {
    long idx = (long)blockIdx.x * 256 + threadIdx.x;
    long base = idx * 8;
    float xv[8];
    *reinterpret_cast<float4*>(xv)     = *reinterpret_cast<const float4*>(fact + base);
    *reinterpret_cast<float4*>(xv + 4) = *reinterpret_cast<const float4*>(fact + base + 4);
    uint32_t p0[4], p1[4];
#pragma unroll
    for (int i = 0; i < 4; ++i) {
        float lo = xv[2 * i], hi = xv[2 * i + 1];
        uint32_t q0 = bf2pack(lo, hi);
        float rlo = lo - bflo(q0), rhi = hi - bfhi(q0);
        p0[i] = q0; p1[i] = bf2pack(rlo, rhi);
    }
    *reinterpret_cast<uint4*>(reinterpret_cast<char*>(g_A0) + base * 2) = make_uint4(p0[0], p0[1], p0[2], p0[3]);
    *reinterpret_cast<uint4*>(reinterpret_cast<char*>(g_A1) + base * 2) = make_uint4(p1[0], p1[1], p1[2], p1[3]);
}

// fq: grid 128 (32 bg x 4 h), 512 threads, k-split 2.
#define FQ_QS   0
#define FQ_WS   (2 * 32 * 66)
#define FQ_PART (FQ_WS + 2 * 4096)
#define FQ_SMEM ((FQ_PART + 2 * 2048) * 4)

__global__ __launch_bounds__(512) void fq_kernel(const float* __restrict__ query) {
    extern __shared__ float fsm[];
    float* qs   = fsm + FQ_QS;
    float* ws   = fsm + FQ_WS;
    float* part = fsm + FQ_PART;

    const int tid = threadIdx.x;
    const int half = tid >> 8;
    const int ht = tid & 255;
    const int h  = blockIdx.x & 3;
    const int bg = blockIdx.x >> 2;
    const int bl = (ht >> 4) * 2;
    const int cq = (ht & 15) * 4;

    float acc[8];
#pragma unroll
    for (int i = 0; i < 8; ++i) acc[i] = 0.f;

    for (int kc4 = 0; kc4 < 4; ++kc4) {
        int kc = half * 4 + kc4;
        __syncthreads();
#pragma unroll
        for (int it = 0; it < 8; ++it) {
            int idx = ht + it * 256;
            int bb = idx >> 6, kk = idx & 63;
            qs[half * 2112 + bb * 66 + kk] = query[(long)(bg * 32 + bb) * DQv + kc * 64 + kk];
        }
#pragma unroll
        for (int it = 0; it < 16; ++it) {
            int idx = ht + it * 256;
            ws[half * 4096 + idx] = g_Wq[(h * DQv + kc * 64 + (idx >> 6)) * DD2 + (idx & 63)];
        }
        __syncthreads();
#pragma unroll 4
        for (int k = 0; k < 64; ++k) {
            float qv0 = qs[half * 2112 + bl * 66 + k];
            float qv1 = qs[half * 2112 + (bl + 1) * 66 + k];
            float4 w4 = *reinterpret_cast<const float4*>(ws + half * 4096 + k * 64 + cq);
            acc[0] += qv0 * w4.x; acc[1] += qv0 * w4.y;
            acc[2] += qv0 * w4.z; acc[3] += qv0 * w4.w;
            acc[4] += qv1 * w4.x; acc[5] += qv1 * w4.y;
            acc[6] += qv1 * w4.z; acc[7] += qv1 * w4.w;
        }
    }
    __syncthreads();
#pragma unroll
    for (int r = 0; r < 2; ++r)
#pragma unroll
        for (int j = 0; j < 4; ++j)
            part[half * 2048 + (bl + r) * 64 + cq + j] = acc[r * 4 + j];
    __syncthreads();
    if (half == 0) {
#pragma unroll
        for (int j = 0; j < 8; ++j) {
            int o = ht * 8 + j;
            int bb = o >> 6, cc = o & 63;
            float val = part[o] + part[2048 + o] + g_bq[h * DD2 + cc];
            g_fq[(long)(bg * 32 + bb) * 256 + h * 64 + cc] = silu_f(val);
        }
    }
}

// ---------------- HMMA main kernel: one CTA per (b,h), 2 CTAs/SM ----------------
// bf16x2 split, 3 passes (a0b0, a0b1, a1b0).
// A tiled 80/80/40; online softmax in v-warps; 8 warps = 4 ng(n32) x 2 mg.
#define AS_SPL 20480
#define BS_OFF 40960
#define BS_SPL 32768
#define SCR_OFF 106496
#define SMEM_BYTES 108544

template<int MT>
__device__ __forceinline__ void gemm32(uint32_t sbase, int nb, int mbase, int lane, float d[][16]) {
#pragma unroll
    for (int mt = 0; mt < MT; ++mt)
#pragma unroll
        for (int i = 0; i < 16; ++i) d[mt][i] = 0.f;

    const uint32_t xr = (uint32_t)(lane & 7);
    const uint32_t arow = (uint32_t)(mbase + (lane & 15)) * 256;
    const uint32_t achk = (uint32_t)(lane >> 4);
    const uint32_t bj  = (uint32_t)(lane >> 4);
    const uint32_t bchk = (uint32_t)((lane >> 3) & 1);
    const uint32_t brow_base = (uint32_t)(nb + bj * 8 + (lane & 7)) * 256;

#pragma unroll 1
    for (int ks = 0; ks < 8; ++ks) {
        uint32_t bf[2][2][4];
        const uint32_t bx = (((uint32_t)(2 * ks) + bchk) ^ xr) * 16;
#pragma unroll
        for (int s = 0; s < 2; ++s)
#pragma unroll
            for (int jp = 0; jp < 2; ++jp)
                ldm_x4(bf[s][jp], sbase + BS_OFF + s * BS_SPL + brow_base + (uint32_t)(jp * 16) * 256 + bx);
        const uint32_t ax = (((uint32_t)(2 * ks) + achk) ^ xr) * 16;
#pragma unroll
        for (int mt = 0; mt < MT; ++mt) {
            const uint32_t aoff = arow + (uint32_t)(mt * 16) * 256 + ax;
            uint32_t a0[4], a1[4];
            ldm_x4(a0, sbase + aoff);
            ldm_x4(a1, sbase + AS_SPL + aoff);
#pragma unroll
            for (int jp = 0; jp < 2; ++jp)
#pragma unroll
                for (int jj = 0; jj < 2; ++jj) {
                    int j = jp * 2 + jj;
                    mma16816(d[mt] + 4 * j, a0, bf[0][jp] + 2 * jj);
                    mma16816(d[mt] + 4 * j, a0, bf[1][jp] + 2 * jj);
                    mma16816(d[mt] + 4 * j, a1, bf[0][jp] + 2 * jj);
                }
        }
    }
}

__global__ __launch_bounds__(256, 2) void mha_hmma_kernel(
    const int* __restrict__ mask, const float* __restrict__ mm,
    const float* __restrict__ tau1, const float* __restrict__ tau2,
    float* __restrict__ out)
{
    extern __shared__ char smem[];
    float* scr = reinterpret_cast<float*>(smem + SCR_OFF);
    float* pd0 = scr;          // [80]
    float* pd1 = scr + 80;     // [80]
    float* lg_s = scr + 160;   // [80]
    float* mo  = scr + 240;    // [2][64]
    float* mp  = scr + 368;    // [2][64]
    float* mS  = scr + 496;    // [4]

    const int tid  = threadIdx.x;
    const int w    = tid >> 5;
    const int lane = tid & 31;
    const int g    = lane >> 2;
    const int t4   = lane & 3;
    const int b = blockIdx.x >> 2;
    const int h = blockIdx.x & 3;
    const int ng = w & 3;
    const int mg = w >> 2;
    const int nb = ng * 32;
    const bool is_f = (ng < 2);
    const uint32_t sbase = smem_u32(smem);

    float bcv[8], fqv[8];
#pragma unroll
    for (int j = 0; j < 4; ++j) {
        int c = nb + j * 8 + t4 * 2;
        bcv[2 * j]     = g_bc[h * 128 + c];
        bcv[2 * j + 1] = g_bc[h * 128 + c + 1];
        if (is_f) {
            fqv[2 * j]     = g_fq[b * 256 + h * 64 + c];
            fqv[2 * j + 1] = g_fq[b * 256 + h * 64 + c + 1];
        } else { fqv[2 * j] = 0.f; fqv[2 * j + 1] = 0.f; }
    }

    const __nv_bfloat16* asrc0 = g_A0 + (long)b * 25600;
    const __nv_bfloat16* asrc1 = g_A1 + (long)b * 25600;

    // ---- stage B (both splits) + A tile0 (80 rows) ----
    {
        const __nv_bfloat16* bsrc[2] = {g_B0 + h * 16384, g_B1 + h * 16384};
#pragma unroll
        for (int it = 0; it < 16; ++it) {
            int idx = tid + it * 256;          // < 4096
            int s = idx >> 11, r = idx & 2047;
            int crow = r >> 4, c = r & 15;
            uint32_t dst = sbase + BS_OFF + s * BS_SPL + crow * 256 + ((c ^ (crow & 7)) * 16);
            cp16(dst, bsrc[s] + crow * 128 + c * 8);
        }
#pragma unroll
        for (int it = 0; it < 10; ++it) {
            int idx = tid + it * 256;          // < 2560
            int s = idx / 1280;
            int r = idx - s * 1280;
            int l = r >> 4, c = r & 15;
            uint32_t dst = sbase + s * AS_SPL + l * 256 + ((c ^ (l & 7)) * 16);
            const __nv_bfloat16* src = (s == 0 ? asrc0 : asrc1) + (long)l * 128 + c * 8;
            cp16(dst, src);
        }
        CP_COMMIT(); CP_WAIT0();
    }
    __syncthreads();

    const float t1a = tau1[h], t1b = tau1[4 + h];
    const float cb1v = tau2[h], cb2v = tau2[4 + h], cb3v = tau2[8 + h];

    float m_run = -FLT_MAX, S_run = 0.f;
    float ov[8], pv[8];
#pragma unroll
    for (int i = 0; i < 8; ++i) { ov[i] = 0.f; pv[i] = 0.f; }

#pragma unroll 1
    for (int t = 0; t < 3; ++t) {
        const int tbase = t * 80;
        const int rowbase = (t < 2) ? (mg ? 48 : 0) : (mg ? 32 : 0);
        const int MT = (t < 2) ? (mg ? 2 : 3) : (mg ? 1 : 2);
        const int rows_t = (t < 2) ? 80 : 40;

        float d[3][16];
        if (t < 2) { if (mg == 0) gemm32<3>(sbase, nb, rowbase, lane, d);
                     else         gemm32<2>(sbase, nb, rowbase, lane, d); }
        else       { if (mg == 0) gemm32<2>(sbase, nb, rowbase, lane, d);
                     else         gemm32<1>(sbase, nb, rowbase, lane, d); }

        if (is_f) {
#pragma unroll
            for (int mt = 0; mt < 3; ++mt) {
                if (mt < MT) {
                    float s0 = 0.f, s1 = 0.f;
#pragma unroll
                    for (int j = 0; j < 4; ++j) {
                        s0 += silu_f(d[mt][4*j]   + bcv[2*j])   * fqv[2*j]
                            + silu_f(d[mt][4*j+1] + bcv[2*j+1]) * fqv[2*j+1];
                        s1 += silu_f(d[mt][4*j+2] + bcv[2*j])   * fqv[2*j]
                            + silu_f(d[mt][4*j+3] + bcv[2*j+1]) * fqv[2*j+1];
                    }
                    s0 += __shfl_xor_sync(0xffffffffu, s0, 1); s0 += __shfl_xor_sync(0xffffffffu, s0, 2);
                    s1 += __shfl_xor_sync(0xffffffffu, s1, 1); s1 += __shfl_xor_sync(0xffffffffu, s1, 2);
                    if (t4 == 0) {
                        float* pdp = (ng == 0) ? pd0 : pd1;
                        pdp[rowbase + mt * 16 + g]     = s0;
                        pdp[rowbase + mt * 16 + g + 8] = s1;
                    }
                }
            }
        }
        __syncthreads();   // A(t) fully consumed; pd visible

        if (t < 2) {
            const int ntb = tbase + 80;
            const int R = (t == 0) ? 80 : 40;
            const int chunks = R * 16;
            for (int idx = tid; idx < 2 * chunks; idx += 256) {
                int s = idx / chunks;
                int r = idx - s * chunks;
                int l = r >> 4, c = r & 15;
                uint32_t dst = sbase + s * AS_SPL + l * 256 + ((c ^ (l & 7)) * 16);
                const __nv_bfloat16* src = (s == 0 ? asrc0 : asrc1) + (long)(ntb + l) * 128 + c * 8;
                cp16(dst, src);
            }
            CP_COMMIT();
        }

        if (tid < rows_t) {
            int l = tbase + tid;
            float dd = pd0[tid] + pd1[tid];
            float mk = (float)mask[b * 200 + l];
            dd += (-1e9f) * (1.f - mk);
            float bias = mm[b * 200 + l] / t1a + mm[204800 + b * 200 + l] / t1b;
            lg_s[tid] = cb1v * dd + cb2v * bias + cb3v * dd * bias;
        }
        __syncthreads();

        if (!is_f) {
#pragma unroll
            for (int mt = 0; mt < 3; ++mt) {
                if (mt < MT) {
                    int loc0 = rowbase + mt * 16 + g;
#pragma unroll
                    for (int half = 0; half < 2; ++half) {
                        int loc = loc0 + half * 8;
                        int l = tbase + loc;
                        if (l < 200) {
                            float lg = lg_s[loc];
                            float mn = fmaxf(m_run, lg);
                            float sc = __expf(m_run - mn);
                            float e  = __expf(lg - mn);
                            S_run = S_run * sc + e;
#pragma unroll
                            for (int j = 0; j < 4; ++j) {
                                float v0 = silu_f(d[mt][4*j + 2*half]     + bcv[2*j]);
                                float v1 = silu_f(d[mt][4*j + 2*half + 1] + bcv[2*j+1]);
                                ov[2*j]   = ov[2*j]   * sc + e * v0;  pv[2*j]   += v0;
                                ov[2*j+1] = ov[2*j+1] * sc + e * v1;  pv[2*j+1] += v1;
                            }
                            m_run = mn;
                        }
                    }
                }
            }
        }
        if (t < 2) CP_WAIT0();
        __syncthreads();
    }

    // ---- merge ----
    if (!is_f) {
#pragma unroll
        for (int off = 4; off <= 16; off <<= 1) {
            float m2 = __shfl_xor_sync(0xffffffffu, m_run, off);
            float S2 = __shfl_xor_sync(0xffffffffu, S_run, off);
            float M = fmaxf(m_run, m2);
            float sa = __expf(m_run - M), sb = __expf(m2 - M);
            S_run = S_run * sa + S2 * sb;
#pragma unroll
            for (int i = 0; i < 8; ++i) {
                float o2 = __shfl_xor_sync(0xffffffffu, ov[i], off);
                float p2 = __shfl_xor_sync(0xffffffffu, pv[i], off);
                ov[i] = ov[i] * sa + o2 * sb;
                pv[i] += p2;
            }
            m_run = M;
        }
        if (lane < 4) {
#pragma unroll
            for (int j = 0; j < 4; ++j) {
                int c = (ng - 2) * 32 + j * 8 + t4 * 2;
                mo[mg * 64 + c]     = ov[2*j];
                mo[mg * 64 + c + 1] = ov[2*j+1];
                mp[mg * 64 + c]     = pv[2*j];
                mp[mg * 64 + c + 1] = pv[2*j+1];
            }
            if (ng == 2 && lane == 0) { mS[mg] = m_run; mS[2 + mg] = S_run; }
        }
    }
    __syncthreads();

    if (tid < 64) {
        float m0 = mS[0], m1 = mS[1];
        float M = fmaxf(m0, m1);
        float e0 = __expf(m0 - M), e1 = __expf(m1 - M);
        float S = mS[2] * e0 + mS[3] * e1;
        float o = mo[tid] * e0 + mo[64 + tid] * e1;
        float p = mp[tid] + mp[64 + tid];
        out[b * 256 + h * 64 + tid] = __fdividef(o, S) + 1e-7f * p;
    }
}

extern "C" void kernel_launch(void* const* d_in, const int* in_sizes, int n_in,
                              void* d_out, int out_size) {
    const float* query = (const float*)d_in[0];
    const float* fact  = (const float*)d_in[1];
    const int*   mask  = (const int*)  d_in[2];
    const float* mm    = (const float*)d_in[3];
    const float* Wq1   = (const float*)d_in[4];
    const float* bq1   = (const float*)d_in[5];
    const float* Wq2   = (const float*)d_in[6];
    const float* bq2   = (const float*)d_in[7];
    const float* Wf1   = (const float*)d_in[8];
    const float* bf1   = (const float*)d_in[9];
    const float* Wf2   = (const float*)d_in[10];
    const float* bf2   = (const float*)d_in[11];
    const float* Wv1   = (const float*)d_in[12];
    const float* bv1   = (const float*)d_in[13];
    const float* Wv2   = (const float*)d_in[14];
    const float* bv2   = (const float*)d_in[15];
    const float* tau1  = (const float*)d_in[16];
    const float* tau2  = (const float*)d_in[17];
    float* out = (float*)d_out;

    cudaFuncSetAttribute(mha_hmma_kernel, cudaFuncAttributeMaxDynamicSharedMemorySize, SMEM_BYTES);
    cudaFuncSetAttribute(fq_kernel, cudaFuncAttributeMaxDynamicSharedMemorySize, FQ_SMEM);

    collapse_q_kernel<<<512, 256>>>(Wq1, bq1, Wq2, bq2);
    collapse_fvT_kernel<<<256, 256>>>(Wf1, bf1, Wf2, bf2, Wv1, bv1, Wv2, bv2);
    presplit_fact<<<12800, 256>>>(fact);
    fq_kernel<<<128, 512, FQ_SMEM>>>(query);
    mha_hmma_kernel<<<BB * HH, 256, SMEM_BYTES>>>(mask, mm, tau1, tau2, out);
}

// round 17
// speedup vs baseline: 1.1362x; 1.0598x over previous
#include <cuda_runtime.h>
#include <cuda_bf16.h>
#include <float.h>
#include <stdint.h>

#define HH 4
#define BB 1024
#define DQv 512
#define DFv 128
#define DD1 128
#define DD2 64

__device__ float g_Wq[HH * DQv * DD2];
__device__ float g_bq[HH * DD2];
__device__ float g_bc[HH * 128];
__device__ float g_fq[BB * HH * DD2];
__device__ __nv_bfloat16 g_B0[HH * 128 * 128];   // [h][c][k]
__device__ __nv_bfloat16 g_B1[HH * 128 * 128];
__device__ __nv_bfloat16 g_A0[(long)BB * 200 * 128];  // [b][l][k]
__device__ __nv_bfloat16 g_A1[(long)BB * 200 * 128];

__device__ __forceinline__ float silu_f(float x) { return __fdividef(x, 1.f + __expf(-x)); }
__device__ __forceinline__ uint32_t smem_u32(const void* p) {
    uint32_t a;
    asm("{ .reg .u64 t; cvta.to.shared.u64 t, %1; cvt.u32.u64 %0, t; }" : "=r"(a) : "l"(p));
    return a;
}
__device__ __forceinline__ uint32_t bf2pack(float lo, float hi) {
    uint32_t r;
    asm("cvt.rn.bf16x2.f32 %0, %1, %2;" : "=r"(r) : "f"(hi), "f"(lo));
    return r;
}
__device__ __forceinline__ float bflo(uint32_t q) { return __uint_as_float(q << 16); }
__device__ __forceinline__ float bfhi(uint32_t q) { return __uint_as_float(q & 0xffff0000u); }

__device__ __forceinline__ void ldm_x4(uint32_t a[4], uint32_t addr) {
    asm volatile("ldmatrix.sync.aligned.m8n8.x4.shared.b16 {%0,%1,%2,%3}, [%4];"
        : "=r"(a[0]), "=r"(a[1]), "=r"(a[2]), "=r"(a[3]) : "r"(addr));
}
__device__ __forceinline__ void mma16816(float d[4], const uint32_t a[4], const uint32_t b[2]) {
    asm volatile(
        "mma.sync.aligned.m16n8k16.row.col.f32.bf16.bf16.f32 "
        "{%0,%1,%2,%3}, {%4,%5,%6,%7}, {%8,%9}, {%0,%1,%2,%3};"
        : "+f"(d[0]), "+f"(d[1]), "+f"(d[2]), "+f"(d[3])
        : "r"(a[0]), "r"(a[1]), "r"(a[2]), "r"(a[3]), "r"(b[0]), "r"(b[1]));
}
__device__ __forceinline__ void cp16(uint32_t dst, const void* src) {
    asm volatile("cp.async.cg.shared.global [%0], [%1], 16;" :: "r"(dst), "l"(src));
}
#define CP_COMMIT()      asm volatile("cp.async.commit_group;" ::: "memory")
#define CP_WAIT0()       asm volatile("cp.async.wait_group 0;" ::: "memory")

// ---------------- fused prep kernel ----------------
// blocks [0, 12800): presplit_fact; [12800, 13312): collapse_q; [13312, 13568): collapse_fvT
__global__ __launch_bounds__(256) void prep_fused(
    const float* __restrict__ fact,
    const float* __restrict__ Wq1, const float* __restrict__ bq1,
    const float* __restrict__ Wq2, const float* __restrict__ bq2,
    const float* __restrict__ Wf1, const float* __restrict__ bf1,
    const float* __restrict__ Wf2, const float* __restrict__ bf2,
    const float* __restrict__ Wv1, const float* __restrict__ bv1,
    const float* __restrict__ Wv2, const float* __restrict__ bv2)
{
    const int bid = blockIdx.x;
    if (bid < 12800) {
        // ---- presplit fact -> bf16x2 images ----
        long idx = (long)bid * 256 + threadIdx.x;
        long base = idx * 8;
        float xv[8];
        *reinterpret_cast<float4*>(xv)     = *reinterpret_cast<const float4*>(fact + base);
        *reinterpret_cast<float4*>(xv + 4) = *reinterpret_cast<const float4*>(fact + base + 4);
        uint32_t p0[4], p1[4];
#pragma unroll
        for (int i = 0; i < 4; ++i) {
            float lo = xv[2 * i], hi = xv[2 * i + 1];
            uint32_t q0 = bf2pack(lo, hi);
            float rlo = lo - bflo(q0), rhi = hi - bfhi(q0);
            p0[i] = q0; p1[i] = bf2pack(rlo, rhi);
        }
        *reinterpret_cast<uint4*>(reinterpret_cast<char*>(g_A0) + base * 2) = make_uint4(p0[0], p0[1], p0[2], p0[3]);
        *reinterpret_cast<uint4*>(reinterpret_cast<char*>(g_A1) + base * 2) = make_uint4(p1[0], p1[1], p1[2], p1[3]);
    } else if (bid < 13312) {
        // ---- collapse_q ----
        int idx = (bid - 12800) * 256 + threadIdx.x;
        int c = idx & 63, k = (idx >> 6) & 511, h = idx >> 15;
        const float* a  = Wq1 + (h * DQv + k) * DD1;
        const float* w2 = Wq2 + h * DD1 * DD2 + c;
        float acc = 0.f;
#pragma unroll 8
        for (int j = 0; j < DD1; ++j) acc += a[j] * w2[j * DD2];
        g_Wq[idx] = acc;
        if (k == 0) {
            float bb = bq2[h * DD2 + c];
            const float* b1p = bq1 + h * DD1;
#pragma unroll 8
            for (int j = 0; j < DD1; ++j) bb += b1p[j] * w2[j * DD2];
            g_bq[h * DD2 + c] = bb;
        }
    } else {
        // ---- collapse_fvT + bf16x2 split ----
        int idx = (bid - 13312) * 256 + threadIdx.x;
        int c = idx & 127, k = (idx >> 7) & 127, h = idx >> 14;
        const float *W1, *W2, *B1, *B2; int cc;
        if (c < 64) { W1 = Wf1; W2 = Wf2; B1 = bf1; B2 = bf2; cc = c; }
        else        { W1 = Wv1; W2 = Wv2; B1 = bv1; B2 = bv2; cc = c - 64; }
        const float* a  = W1 + (h * DFv + k) * DD1;
        const float* w2 = W2 + h * DD1 * DD2 + cc;
        float acc = 0.f;
#pragma unroll 8
        for (int j = 0; j < DD1; ++j) acc += a[j] * w2[j * DD2];
        int o = h * 16384 + c * 128 + k;
        __nv_bfloat16 q0 = __float2bfloat16(acc);
        float r1 = acc - __bfloat162float(q0);
        g_B0[o] = q0; g_B1[o] = __float2bfloat16(r1);
        if (k == 0) {
            float bb = B2[h * DD2 + cc];
            const float* b1p = B1 + h * DD1;
#pragma unroll 8
            for (int j = 0; j < DD1; ++j) bb += b1p[j] * w2[j * DD2];
            g_bc[h * 128 + c] = bb;
        }
    }
}

// fq: grid 128 (32 bg x 4 h), 512 threads, k-split 2.
#define FQ_QS   0
#define FQ_WS   (2 * 32 * 66)
#define FQ_PART (FQ_WS + 2 * 4096)
#define FQ_SMEM ((FQ_PART + 2 * 2048) * 4)

__global__ __launch_bounds__(512) void fq_kernel(const float* __restrict__ query) {
    extern __shared__ float fsm[];
    float* qs   = fsm + FQ_QS;
    float* ws   = fsm + FQ_WS;
    float* part = fsm + FQ_PART;

    const int tid = threadIdx.x;
    const int half = tid >> 8;
    const int ht = tid & 255;
    const int h  = blockIdx.x & 3;
    const int bg = blockIdx.x >> 2;
    const int bl = (ht >> 4) * 2;
    const int cq = (ht & 15) * 4;

    float acc[8];
#pragma unroll
    for (int i = 0; i < 8; ++i) acc[i] = 0.f;

    for (int kc4 = 0; kc4 < 4; ++kc4) {
        int kc = half * 4 + kc4;
        __syncthreads();
#pragma unroll
        for (int it = 0; it < 8; ++it) {
            int idx = ht + it * 256;
            int bb = idx >> 6, kk = idx & 63;
            qs[half * 2112 + bb * 66 + kk] = query[(long)(bg * 32 + bb) * DQv + kc * 64 + kk];
        }
#pragma unroll
        for (int it = 0; it < 16; ++it) {
            int idx = ht + it * 256;
            ws[half * 4096 + idx] = g_Wq[(h * DQv + kc * 64 + (idx >> 6)) * DD2 + (idx & 63)];
        }
        __syncthreads();
#pragma unroll 4
        for (int k = 0; k < 64; ++k) {
            float qv0 = qs[half * 2112 + bl * 66 + k];
            float qv1 = qs[half * 2112 + (bl + 1) * 66 + k];
            float4 w4 = *reinterpret_cast<const float4*>(ws + half * 4096 + k * 64 + cq);
            acc[0] += qv0 * w4.x; acc[1] += qv0 * w4.y;
            acc[2] += qv0 * w4.z; acc[3] += qv0 * w4.w;
            acc[4] += qv1 * w4.x; acc[5] += qv1 * w4.y;
            acc[6] += qv1 * w4.z; acc[7] += qv1 * w4.w;
        }
    }
    __syncthreads();
#pragma unroll
    for (int r = 0; r < 2; ++r)
#pragma unroll
        for (int j = 0; j < 4; ++j)
            part[half * 2048 + (bl + r) * 64 + cq + j] = acc[r * 4 + j];
    __syncthreads();
    if (half == 0) {
#pragma unroll
        for (int j = 0; j < 8; ++j) {
            int o = ht * 8 + j;
            int bb = o >> 6, cc = o & 63;
            float val = part[o] + part[2048 + o] + g_bq[h * DD2 + cc];
            g_fq[(long)(bg * 32 + bb) * 256 + h * 64 + cc] = silu_f(val);
        }
    }
}

// ---------------- HMMA main kernel (R16 best, unchanged) ----------------
#define AS_SPL 20480
#define BS_OFF 40960
#define BS_SPL 32768
#define SCR_OFF 106496
#define SMEM_BYTES 108544

template<int MT>
__device__ __forceinline__ void gemm32(uint32_t sbase, int nb, int mbase, int lane, float d[][16]) {
#pragma unroll
    for (int mt = 0; mt < MT; ++mt)
#pragma unroll
        for (int i = 0; i < 16; ++i) d[mt][i] = 0.f;

    const uint32_t xr = (uint32_t)(lane & 7);
    const uint32_t arow = (uint32_t)(mbase + (lane & 15)) * 256;
    const uint32_t achk = (uint32_t)(lane >> 4);
    const uint32_t bj  = (uint32_t)(lane >> 4);
    const uint32_t bchk = (uint32_t)((lane >> 3) & 1);
    const uint32_t brow_base = (uint32_t)(nb + bj * 8 + (lane & 7)) * 256;

#pragma unroll 1
    for (int ks = 0; ks < 8; ++ks) {
        uint32_t bf[2][2][4];
        const uint32_t bx = (((uint32_t)(2 * ks) + bchk) ^ xr) * 16;
#pragma unroll
        for (int s = 0; s < 2; ++s)
#pragma unroll
            for (int jp = 0; jp < 2; ++jp)
                ldm_x4(bf[s][jp], sbase + BS_OFF + s * BS_SPL + brow_base + (uint32_t)(jp * 16) * 256 + bx);
        const uint32_t ax = (((uint32_t)(2 * ks) + achk) ^ xr) * 16;
#pragma unroll
        for (int mt = 0; mt < MT; ++mt) {
            const uint32_t aoff = arow + (uint32_t)(mt * 16) * 256 + ax;
            uint32_t a0[4], a1[4];
            ldm_x4(a0, sbase + aoff);
            ldm_x4(a1, sbase + AS_SPL + aoff);
#pragma unroll
            for (int jp = 0; jp < 2; ++jp)
#pragma unroll
                for (int jj = 0; jj < 2; ++jj) {
                    int j = jp * 2 + jj;
                    mma16816(d[mt] + 4 * j, a0, bf[0][jp] + 2 * jj);
                    mma16816(d[mt] + 4 * j, a0, bf[1][jp] + 2 * jj);
                    mma16816(d[mt] + 4 * j, a1, bf[0][jp] + 2 * jj);
                }
        }
    }
}

__global__ __launch_bounds__(256, 2) void mha_hmma_kernel(
    const int* __restrict__ mask, const float* __restrict__ mm,
    const float* __restrict__ tau1, const float* __restrict__ tau2,
    float* __restrict__ out)
{
    extern __shared__ char smem[];
    float* scr = reinterpret_cast<float*>(smem + SCR_OFF);
    float* pd0 = scr;          // [80]
    float* pd1 = scr + 80;     // [80]
    float* lg_s = scr + 160;   // [80]
    float* mo  = scr + 240;    // [2][64]
    float* mp  = scr + 368;    // [2][64]
    float* mS  = scr + 496;    // [4]

    const int tid  = threadIdx.x;
    const int w    = tid >> 5;
    const int lane = tid & 31;
    const int g    = lane >> 2;
    const int t4   = lane & 3;
    const int b = blockIdx.x >> 2;
    const int h = blockIdx.x & 3;
    const int ng = w & 3;
    const int mg = w >> 2;
    const int nb = ng * 32;
    const bool is_f = (ng < 2);
    const uint32_t sbase = smem_u32(smem);

    float bcv[8], fqv[8];
#pragma unroll
    for (int j = 0; j < 4; ++j) {
        int c = nb + j * 8 + t4 * 2;
        bcv[2 * j]     = g_bc[h * 128 + c];
        bcv[2 * j + 1] = g_bc[h * 128 + c + 1];
        if (is_f) {
            fqv[2 * j]     = g_fq[b * 256 + h * 64 + c];
            fqv[2 * j + 1] = g_fq[b * 256 + h * 64 + c + 1];
        } else { fqv[2 * j] = 0.f; fqv[2 * j + 1] = 0.f; }
    }

    const __nv_bfloat16* asrc0 = g_A0 + (long)b * 25600;
    const __nv_bfloat16* asrc1 = g_A1 + (long)b * 25600;

    // ---- stage B (both splits) + A tile0 (80 rows) ----
    {
        const __nv_bfloat16* bsrc[2] = {g_B0 + h * 16384, g_B1 + h * 16384};
#pragma unroll
        for (int it = 0; it < 16; ++it) {
            int idx = tid + it * 256;
            int s = idx >> 11, r = idx & 2047;
            int crow = r >> 4, c = r & 15;
            uint32_t dst = sbase + BS_OFF + s * BS_SPL + crow * 256 + ((c ^ (crow & 7)) * 16);
            cp16(dst, bsrc[s] + crow * 128 + c * 8);
        }
#pragma unroll
        for (int it = 0; it < 10; ++it) {
            int idx = tid + it * 256;
            int s = idx / 1280;
            int r = idx - s * 1280;
            int l = r >> 4, c = r & 15;
            uint32_t dst = sbase + s * AS_SPL + l * 256 + ((c ^ (l & 7)) * 16);
            const __nv_bfloat16* src = (s == 0 ? asrc0 : asrc1) + (long)l * 128 + c * 8;
            cp16(dst, src);
        }
        CP_COMMIT(); CP_WAIT0();
    }
    __syncthreads();

    const float t1a = tau1[h], t1b = tau1[4 + h];
    const float cb1v = tau2[h], cb2v = tau2[4 + h], cb3v = tau2[8 + h];

    float m_run = -FLT_MAX, S_run = 0.f;
    float ov[8], pv[8];
#pragma unroll
    for (int i = 0; i < 8; ++i) { ov[i] = 0.f; pv[i] = 0.f; }

#pragma unroll 1
    for (int t = 0; t < 3; ++t) {
        const int tbase = t * 80;
        const int rowbase = (t < 2) ? (mg ? 48 : 0) : (mg ? 32 : 0);
        const int MT = (t < 2) ? (mg ? 2 : 3) : (mg ? 1 : 2);
        const int rows_t = (t < 2) ? 80 : 40;

        float d[3][16];
        if (t < 2) { if (mg == 0) gemm32<3>(sbase, nb, rowbase, lane, d);
                     else         gemm32<2>(sbase, nb, rowbase, lane, d); }
        else       { if (mg == 0) gemm32<2>(sbase, nb, rowbase, lane, d);
                     else         gemm32<1>(sbase, nb, rowbase, lane, d); }

        if (is_f) {
#pragma unroll
            for (int mt = 0; mt < 3; ++mt) {
                if (mt < MT) {
                    float s0 = 0.f, s1 = 0.f;
#pragma unroll
                    for (int j = 0; j < 4; ++j) {
                        s0 += silu_f(d[mt][4*j]   + bcv[2*j])   * fqv[2*j]
                            + silu_f(d[mt][4*j+1] + bcv[2*j+1]) * fqv[2*j+1];
                        s1 += silu_f(d[mt][4*j+2] + bcv[2*j])   * fqv[2*j]
                            + silu_f(d[mt][4*j+3] + bcv[2*j+1]) * fqv[2*j+1];
                    }
                    s0 += __shfl_xor_sync(0xffffffffu, s0, 1); s0 += __shfl_xor_sync(0xffffffffu, s0, 2);
                    s1 += __shfl_xor_sync(0xffffffffu, s1, 1); s1 += __shfl_xor_sync(0xffffffffu, s1, 2);
                    if (t4 == 0) {
                        float* pdp = (ng == 0) ? pd0 : pd1;
                        pdp[rowbase + mt * 16 + g]     = s0;
                        pdp[rowbase + mt * 16 + g + 8] = s1;
                    }
                }
            }
        }
        __syncthreads();   // A(t) fully consumed; pd visible

        if (t < 2) {
            const int ntb = tbase + 80;
            const int R = (t == 0) ? 80 : 40;
            const int chunks = R * 16;
            for (int idx = tid; idx < 2 * chunks; idx += 256) {
                int s = idx / chunks;
                int r = idx - s * chunks;
                int l = r >> 4, c = r & 15;
                uint32_t dst = sbase + s * AS_SPL + l * 256 + ((c ^ (l & 7)) * 16);
                const __nv_bfloat16* src = (s == 0 ? asrc0 : asrc1) + (long)(ntb + l) * 128 + c * 8;
                cp16(dst, src);
            }
            CP_COMMIT();
        }

        if (tid < rows_t) {
            int l = tbase + tid;
            float dd = pd0[tid] + pd1[tid];
            float mk = (float)mask[b * 200 + l];
            dd += (-1e9f) * (1.f - mk);
            float bias = mm[b * 200 + l] / t1a + mm[204800 + b * 200 + l] / t1b;
            lg_s[tid] = cb1v * dd + cb2v * bias + cb3v * dd * bias;
        }
        __syncthreads();

        if (!is_f) {
#pragma unroll
            for (int mt = 0; mt < 3; ++mt) {
                if (mt < MT) {
                    int loc0 = rowbase + mt * 16 + g;
#pragma unroll
                    for (int half = 0; half < 2; ++half) {
                        int loc = loc0 + half * 8;
                        int l = tbase + loc;
                        if (l < 200) {
                            float lg = lg_s[loc];
                            float mn = fmaxf(m_run, lg);
                            float sc = __expf(m_run - mn);
                            float e  = __expf(lg - mn);
                            S_run = S_run * sc + e;
#pragma unroll
                            for (int j = 0; j < 4; ++j) {
                                float v0 = silu_f(d[mt][4*j + 2*half]     + bcv[2*j]);
                                float v1 = silu_f(d[mt][4*j + 2*half + 1] + bcv[2*j+1]);
                                ov[2*j]   = ov[2*j]   * sc + e * v0;  pv[2*j]   += v0;
                                ov[2*j+1] = ov[2*j+1] * sc + e * v1;  pv[2*j+1] += v1;
                            }
                            m_run = mn;
                        }
                    }
                }
            }
        }
        if (t < 2) CP_WAIT0();
        __syncthreads();
    }

    // ---- merge ----
    if (!is_f) {
#pragma unroll
        for (int off = 4; off <= 16; off <<= 1) {
            float m2 = __shfl_xor_sync(0xffffffffu, m_run, off);
            float S2 = __shfl_xor_sync(0xffffffffu, S_run, off);
            float M = fmaxf(m_run, m2);
            float sa = __expf(m_run - M), sb = __expf(m2 - M);
            S_run = S_run * sa + S2 * sb;
#pragma unroll
            for (int i = 0; i < 8; ++i) {
                float o2 = __shfl_xor_sync(0xffffffffu, ov[i], off);
                float p2 = __shfl_xor_sync(0xffffffffu, pv[i], off);
                ov[i] = ov[i] * sa + o2 * sb;
                pv[i] += p2;
            }
            m_run = M;
        }
        if (lane < 4) {
#pragma unroll
            for (int j = 0; j < 4; ++j) {
                int c = (ng - 2) * 32 + j * 8 + t4 * 2;
                mo[mg * 64 + c]     = ov[2*j];
                mo[mg * 64 + c + 1] = ov[2*j+1];
                mp[mg * 64 + c]     = pv[2*j];
                mp[mg * 64 + c + 1] = pv[2*j+1];
            }
            if (ng == 2 && lane == 0) { mS[mg] = m_run; mS[2 + mg] = S_run; }
        }
    }
    __syncthreads();

    if (tid < 64) {
        float m0 = mS[0], m1 = mS[1];
        float M = fmaxf(m0, m1);
        float e0 = __expf(m0 - M), e1 = __expf(m1 - M);
        float S = mS[2] * e0 + mS[3] * e1;
        float o = mo[tid] * e0 + mo[64 + tid] * e1;
        float p = mp[tid] + mp[64 + tid];
        out[b * 256 + h * 64 + tid] = __fdividef(o, S) + 1e-7f * p;
    }
}

extern "C" void kernel_launch(void* const* d_in, const int* in_sizes, int n_in,
                              void* d_out, int out_size) {
    const float* query = (const float*)d_in[0];
    const float* fact  = (const float*)d_in[1];
    const int*   mask  = (const int*)  d_in[2];
    const float* mm    = (const float*)d_in[3];
    const float* Wq1   = (const float*)d_in[4];
    const float* bq1   = (const float*)d_in[5];
    const float* Wq2   = (const float*)d_in[6];
    const float* bq2   = (const float*)d_in[7];
    const float* Wf1   = (const float*)d_in[8];
    const float* bf1   = (const float*)d_in[9];
    const float* Wf2   = (const float*)d_in[10];
    const float* bf2   = (const float*)d_in[11];
    const float* Wv1   = (const float*)d_in[12];
    const float* bv1   = (const float*)d_in[13];
    const float* Wv2   = (const float*)d_in[14];
    const float* bv2   = (const float*)d_in[15];
    const float* tau1  = (const float*)d_in[16];
    const float* tau2  = (const float*)d_in[17];
    float* out = (float*)d_out;

    cudaFuncSetAttribute(mha_hmma_kernel, cudaFuncAttributeMaxDynamicSharedMemorySize, SMEM_BYTES);
    cudaFuncSetAttribute(fq_kernel, cudaFuncAttributeMaxDynamicSharedMemorySize, FQ_SMEM);

    prep_fused<<<13568, 256>>>(fact, Wq1, bq1, Wq2, bq2,
                               Wf1, bf1, Wf2, bf2, Wv1, bv1, Wv2, bv2);
    fq_kernel<<<128, 512, FQ_SMEM>>>(query);
    mha_hmma_kernel<<<BB * HH, 256, SMEM_BYTES>>>(mask, mm, tau1, tau2, out);
}